// round 16
// baseline (speedup 1.0000x reference)
#include <cuda_runtime.h>
#include <cstdint>

#define NROWS 8192
#define NCOLS 2048
#define BINS  30

#define K1_THREADS 512          // one column per thread
#define COL_TILES  (NCOLS / K1_THREADS)   // 4
#define CHUNKS     74
#define ROWS_PER_CHUNK 111      // 74*111 = 8214 >= 8192
#define FXSCALE 4096.0f

// ---- scratch (static device globals: allocation-free) ----
__device__ unsigned g_scratch[(size_t)CHUNKS * BINS * NCOLS]; // 18.2 MB packed per-chunk hists
__device__ unsigned g_cnt[BINS * NCOLS];
__device__ unsigned g_sumfx[BINS * NCOLS];
__device__ double   g_part[8];

// =====================================================================
// K1: fused pass — per-thread private histogram of (count, sum bce)
// hist layout: hist[bin * 512 + tid]  (conflict-free: lanes consecutive)
// packed u32:  bits[31:24] = count, bits[23:0] = round(bce * 4096)
// =====================================================================
__global__ __launch_bounds__(K1_THREADS, 2)
void ghmc_k1(const float* __restrict__ preds, const int* __restrict__ targets)
{
    extern __shared__ unsigned hist[]; // BINS * 512 u32 = 61440 B
    const int t = threadIdx.x;

    #pragma unroll
    for (int b = 0; b < BINS; b++) hist[b * K1_THREADS + t] = 0u;
    // no __syncthreads needed: hist slots are strictly per-thread

    const int c  = blockIdx.x * K1_THREADS + t;
    const int r0 = blockIdx.y * ROWS_PER_CHUNK;
    const int r1 = min(r0 + ROWS_PER_CHUNK, NROWS);

    const float* __restrict__ pp = preds   + (size_t)r0 * NCOLS + c;
    const int*   __restrict__ tp = targets + (size_t)r0 * NCOLS + c;

    const float LN2 = 0.6931471805599453f;

    #pragma unroll 4
    for (int r = r0; r < r1; r++) {
        float p  = *pp;  pp += NCOLS;
        int   tv = *tp;  tp += NCOLS;

        float ap = fabsf(p);
        float a  = __expf(-ap);                 // e^{-|p|}   (MUFU.EX2)
        float u  = 1.0f + a;
        float r30 = __fdividef(30.0f, u);       // 30/(1+a)   (MUFU.RCP)

        // x = (t==0) ? p : -p ;  cpos = (x >= 0)
        bool cpos = (p >= 0.0f) == (tv == 0);

        // g*30 = 30*sigmoid(x):  x>=0 -> 30/(1+a) ; x<0 -> 30a/(1+a)
        float g30 = cpos ? r30 : r30 * a;
        int bin = (int)g30;                     // g30 >= 0
        bin = min(bin, BINS - 1);

        // bce = log(1+e^p) - p*t = ln(1+e^{-|p|}) + (x>=0 ? |p| : 0)
        float bce = fmaf(__log2f(u), LN2, cpos ? ap : 0.0f);  // (MUFU.LG2)
        unsigned fx = __float2uint_rn(bce * FXSCALE);

        hist[bin * K1_THREADS + t] += fx + 0x01000000u;
    }

    // coalesced write of this chunk's partial hist
    unsigned* out = g_scratch + (size_t)blockIdx.y * (BINS * NCOLS)
                              + (size_t)blockIdx.x * K1_THREADS + t;
    #pragma unroll
    for (int b = 0; b < BINS; b++)
        out[(size_t)b * NCOLS] = hist[b * K1_THREADS + t];
}

// =====================================================================
// K2: reduce chunk partials -> counts, fixed-point bce sums  (exact ints)
// =====================================================================
__global__ void ghmc_k2()
{
    int j = blockIdx.x * blockDim.x + threadIdx.x; // < BINS*NCOLS = 61440
    unsigned cnt = 0, sm = 0;
    #pragma unroll 4
    for (int ch = 0; ch < CHUNKS; ch++) {
        unsigned v = g_scratch[(size_t)ch * (BINS * NCOLS) + j];
        cnt += v >> 24;
        sm  += v & 0x00FFFFFFu;
    }
    g_cnt[j]   = cnt;
    g_sumfx[j] = sm;
}

// =====================================================================
// K3: per-column n, acc_new, weights; reduce w*S per column -> 8 block partials
// =====================================================================
__global__ void ghmc_k3(const float* __restrict__ acc_sum)
{
    const int t = threadIdx.x;
    const int c = blockIdx.x * blockDim.x + t;

    int n = 0;
    #pragma unroll
    for (int b = 0; b < BINS; b++) n += (g_cnt[b * NCOLS + c] >= 1u);
    float nf = (float)max(n, 1);

    double colsum = 0.0;
    #pragma unroll
    for (int b = 0; b < BINS; b++) {
        unsigned cnt = g_cnt[b * NCOLS + c];
        if (cnt) {
            float acc = 0.75f * acc_sum[b * NCOLS + c] + 0.25f * (float)cnt;
            float S   = (float)g_sumfx[b * NCOLS + c] * (1.0f / FXSCALE);
            float w   = 8192.0f / (acc * nf);
            colsum += (double)(w * S);
        }
    }

    __shared__ double sd[256];
    sd[t] = colsum;
    __syncthreads();
    #pragma unroll
    for (int s = 128; s > 0; s >>= 1) {
        if (t < s) sd[t] += sd[t + s];
        __syncthreads();
    }
    if (t == 0) g_part[blockIdx.x] = sd[0];
}

// =====================================================================
// K4: final scalar
// =====================================================================
__global__ void ghmc_k4(float* out)
{
    double tot = 0.0;
    #pragma unroll
    for (int i = 0; i < 8; i++) tot += g_part[i];
    out[0] = (float)(tot / ((double)NROWS * (double)NCOLS));
}

extern "C" void kernel_launch(void* const* d_in, const int* in_sizes, int n_in,
                              void* d_out, int out_size)
{
    const float* preds   = (const float*)d_in[0];
    const int*   targets = (const int*)  d_in[1];
    const float* acc_sum = (const float*)d_in[2];
    float*       out     = (float*)d_out;

    const int smem = BINS * K1_THREADS * sizeof(unsigned); // 61440 B
    cudaFuncSetAttribute(ghmc_k1, cudaFuncAttributeMaxDynamicSharedMemorySize, smem);

    dim3 g1(COL_TILES, CHUNKS);              // 4 x 74 = 296 blocks = 2/SM, one wave
    ghmc_k1<<<g1, K1_THREADS, smem>>>(preds, targets);

    ghmc_k2<<<(BINS * NCOLS) / 256, 256>>>();
    ghmc_k3<<<NCOLS / 256, 256>>>(acc_sum);
    ghmc_k4<<<1, 1>>>(out);
}

// round 17
// speedup vs baseline: 1.0049x; 1.0049x over previous
#include <cuda_runtime.h>
#include <cstdint>

#define NROWS 8192
#define NCOLS 2048
#define BINS  30

#define K1_THREADS 512          // one column per thread
#define COL_TILES  (NCOLS / K1_THREADS)   // 4
#define CHUNKS     74
#define ROWS_PER_CHUNK 111      // 74*111 = 8214 >= 8192
#define FXSCALE 4096.0f

// ---- scratch (static device globals: allocation-free) ----
__device__ unsigned g_scratch[(size_t)CHUNKS * BINS * NCOLS]; // 18.2 MB packed per-chunk hists
__device__ unsigned g_cnt[BINS * NCOLS];
__device__ unsigned g_sumfx[BINS * NCOLS];
__device__ double   g_part[8];

// =====================================================================
// K1: fused pass — per-thread private histogram of (count, sum bce)
// hist layout: hist[bin * 512 + tid]  (conflict-free: lanes consecutive)
// packed u32:  bits[31:24] = count, bits[23:0] = round(bce * 4096)
// =====================================================================
__global__ __launch_bounds__(K1_THREADS, 2)
void ghmc_k1(const float* __restrict__ preds, const int* __restrict__ targets)
{
    extern __shared__ unsigned hist[]; // BINS * 512 u32 = 61440 B
    const int t = threadIdx.x;

    #pragma unroll
    for (int b = 0; b < BINS; b++) hist[b * K1_THREADS + t] = 0u;
    // no __syncthreads needed: hist slots are strictly per-thread

    const int c  = blockIdx.x * K1_THREADS + t;
    const int r0 = blockIdx.y * ROWS_PER_CHUNK;
    const int r1 = min(r0 + ROWS_PER_CHUNK, NROWS);

    const float* __restrict__ pp = preds   + (size_t)r0 * NCOLS + c;
    const int*   __restrict__ tp = targets + (size_t)r0 * NCOLS + c;

    const float LN2 = 0.6931471805599453f;

    #pragma unroll 4
    for (int r = r0; r < r1; r++) {
        float p  = *pp;  pp += NCOLS;
        int   tv = *tp;  tp += NCOLS;

        float ap = fabsf(p);
        float a  = __expf(-ap);                 // e^{-|p|}   (MUFU.EX2)
        float u  = 1.0f + a;
        float r30 = __fdividef(30.0f, u);       // 30/(1+a)   (MUFU.RCP)

        // x = (t==0) ? p : -p ;  cpos = (x >= 0)
        bool cpos = (p >= 0.0f) == (tv == 0);

        // g*30 = 30*sigmoid(x):  x>=0 -> 30/(1+a) ; x<0 -> 30a/(1+a)
        float g30 = cpos ? r30 : r30 * a;
        int bin = (int)g30;                     // g30 >= 0
        bin = min(bin, BINS - 1);

        // bce = log(1+e^p) - p*t = ln(1+e^{-|p|}) + (x>=0 ? |p| : 0)
        float bce = fmaf(__log2f(u), LN2, cpos ? ap : 0.0f);  // (MUFU.LG2)
        unsigned fx = __float2uint_rn(bce * FXSCALE);

        hist[bin * K1_THREADS + t] += fx + 0x01000000u;
    }

    // coalesced write of this chunk's partial hist
    unsigned* out = g_scratch + (size_t)blockIdx.y * (BINS * NCOLS)
                              + (size_t)blockIdx.x * K1_THREADS + t;
    #pragma unroll
    for (int b = 0; b < BINS; b++)
        out[(size_t)b * NCOLS] = hist[b * K1_THREADS + t];
}

// =====================================================================
// K2: reduce chunk partials -> counts, fixed-point bce sums  (exact ints)
// =====================================================================
__global__ void ghmc_k2()
{
    int j = blockIdx.x * blockDim.x + threadIdx.x; // < BINS*NCOLS = 61440
    unsigned cnt = 0, sm = 0;
    #pragma unroll 4
    for (int ch = 0; ch < CHUNKS; ch++) {
        unsigned v = g_scratch[(size_t)ch * (BINS * NCOLS) + j];
        cnt += v >> 24;
        sm  += v & 0x00FFFFFFu;
    }
    g_cnt[j]   = cnt;
    g_sumfx[j] = sm;
}

// =====================================================================
// K3: per-column n, acc_new, weights; reduce w*S per column -> 8 block partials
// =====================================================================
__global__ void ghmc_k3(const float* __restrict__ acc_sum)
{
    const int t = threadIdx.x;
    const int c = blockIdx.x * blockDim.x + t;

    int n = 0;
    #pragma unroll
    for (int b = 0; b < BINS; b++) n += (g_cnt[b * NCOLS + c] >= 1u);
    float nf = (float)max(n, 1);

    double colsum = 0.0;
    #pragma unroll
    for (int b = 0; b < BINS; b++) {
        unsigned cnt = g_cnt[b * NCOLS + c];
        if (cnt) {
            float acc = 0.75f * acc_sum[b * NCOLS + c] + 0.25f * (float)cnt;
            float S   = (float)g_sumfx[b * NCOLS + c] * (1.0f / FXSCALE);
            float w   = 8192.0f / (acc * nf);
            colsum += (double)(w * S);
        }
    }

    __shared__ double sd[256];
    sd[t] = colsum;
    __syncthreads();
    #pragma unroll
    for (int s = 128; s > 0; s >>= 1) {
        if (t < s) sd[t] += sd[t + s];
        __syncthreads();
    }
    if (t == 0) g_part[blockIdx.x] = sd[0];
}

// =====================================================================
// K4: final scalar
// =====================================================================
__global__ void ghmc_k4(float* out)
{
    double tot = 0.0;
    #pragma unroll
    for (int i = 0; i < 8; i++) tot += g_part[i];
    out[0] = (float)(tot / ((double)NROWS * (double)NCOLS));
}

extern "C" void kernel_launch(void* const* d_in, const int* in_sizes, int n_in,
                              void* d_out, int out_size)
{
    const float* preds   = (const float*)d_in[0];
    const int*   targets = (const int*)  d_in[1];
    const float* acc_sum = (const float*)d_in[2];
    float*       out     = (float*)d_out;

    const int smem = BINS * K1_THREADS * sizeof(unsigned); // 61440 B
    cudaFuncSetAttribute(ghmc_k1, cudaFuncAttributeMaxDynamicSharedMemorySize, smem);

    dim3 g1(COL_TILES, CHUNKS);              // 4 x 74 = 296 blocks = 2/SM, one wave
    ghmc_k1<<<g1, K1_THREADS, smem>>>(preds, targets);

    ghmc_k2<<<(BINS * NCOLS) / 256, 256>>>();
    ghmc_k3<<<NCOLS / 256, 256>>>(acc_sum);
    ghmc_k4<<<1, 1>>>(out);
}